// round 4
// baseline (speedup 1.0000x reference)
#include <cuda_runtime.h>
#include <cstdint>

#define Bdim 32
#define Kdim 17
#define Hdim 160
#define Wdim 160
#define HW   (Hdim*Wdim)
#define W4   (Wdim/4)
#define NG   (HW/4)
#define Pn   30
#define Sn   10
#define Ln   19
#define NCH  (Bdim*Kdim)
#define T1   256
#define T2   512
#define NBINS 1024
#define CAP   6144
#define SCAP  192
#define SLABS 4
#define RPS   (Hdim/SLABS)
#define GPSLAB (RPS*W4)
#define SLCAP 2560
#define NEGF  (-1.0e30f)

__constant__ int c_skel_a[Ln] = {15,13,16,14,11, 5, 6, 5, 5, 6, 7, 8, 1, 0, 0, 1, 2, 3, 4};
__constant__ int c_skel_b[Ln] = {13,11,14,12,12,11,12, 6, 7, 8, 9,10, 2, 1, 2, 3, 4, 5, 6};

// per-channel candidate scratch (static device memory: no allocation)
__device__ unsigned long long g_list[NCH][CAP];
__device__ int g_cnt[NCH];

// ---------------- cp.async helpers ----------------
__device__ __forceinline__ void cp16(void* s, const void* g) {
    unsigned sa = (unsigned)__cvta_generic_to_shared(s);
    asm volatile("cp.async.cg.shared.global [%0], [%1], 16;\n" :: "r"(sa), "l"(g));
}
__device__ __forceinline__ void cp_commit() { asm volatile("cp.async.commit_group;\n"); }
template <int N>
__device__ __forceinline__ void cp_wait() { asm volatile("cp.async.wait_group %0;\n" :: "n"(N)); }

// monotone bin: v = h^9 (uniform-izes max-of-9 peak-score distribution)
__device__ __forceinline__ int bin_of(float h) {
    float h2 = h * h;
    float h4 = h2 * h2;
    float v  = h4 * h4 * h;
    int b = (int)(v * (float)NBINS);
    return b < 0 ? 0 : (b > NBINS - 1 ? NBINS - 1 : b);
}

__device__ __forceinline__ float max3(float a, float b, float c) {
    return fmaxf(fmaxf(a, b), c);
}

// ---------------------------------------------------------------------------
__global__ void init_kernel() {
    if (threadIdx.x < NCH) g_cnt[threadIdx.x] = 0;
}

// ---------------------------------------------------------------------------
// Detect: one block per (channel, row-slab).  Streams its slab (+halo rows via
// L1), branchless 3x3 NMS, smem candidate buffer, single global atomic flush.
// ---------------------------------------------------------------------------
__global__ void __launch_bounds__(T1) detect_kernel(const float* __restrict__ heat)
{
    __shared__ unsigned long long slist[SLCAP];
    __shared__ int s_cnt, s_base;

    const int ch   = blockIdx.x / SLABS;
    const int slab = blockIdx.x - ch * SLABS;
    const float* hp = heat + (size_t)ch * HW;
    const float4* hp4 = (const float4*)hp;
    const int lane = threadIdx.x & 31;
    const int y0 = slab * RPS;

    if (threadIdx.x == 0) s_cnt = 0;
    __syncthreads();

    const int ITS = (GPSLAB + T1 - 1) / T1;     // 7
    for (int it = 0; it < ITS; ++it) {
        int gl = it * T1 + threadIdx.x;
        bool in = gl < GPSLAB;
        int yy = gl / W4;
        int xq = gl - yy * W4;
        int y  = y0 + yy;
        int g  = y * W4 + xq;
        int i  = g * 4;

        bool up = in && (y > 0), dn = in && (y < Hdim - 1);
        bool lf = in && (xq > 0), rt = in && (xq < W4 - 1);

        float4 nf = make_float4(NEGF, NEGF, NEGF, NEGF);
        float4 C = in ? hp4[g] : nf;
        float4 U = up ? hp4[g - W4] : nf;
        float4 D = dn ? hp4[g + W4] : nf;
        float lC =  lf        ? __ldg(hp + i - 1)        : NEGF;
        float rC =  rt        ? __ldg(hp + i + 4)        : NEGF;
        float lU = (lf && up) ? __ldg(hp + i - Wdim - 1) : NEGF;
        float rU = (rt && up) ? __ldg(hp + i - Wdim + 4) : NEGF;
        float lD = (lf && dn) ? __ldg(hp + i + Wdim - 1) : NEGF;
        float rD = (rt && dn) ? __ldg(hp + i + Wdim + 4) : NEGF;

        float wU[6] = {lU, U.x, U.y, U.z, U.w, rU};
        float wC[6] = {lC, C.x, C.y, C.z, C.w, rC};
        float wD[6] = {lD, D.x, D.y, D.z, D.w, rD};

        #pragma unroll
        for (int j = 0; j < 4; ++j) {
            float h  = wC[j + 1];
            float nm = fmaxf(max3(wU[j], wU[j + 1], wU[j + 2]),
                             fmaxf(max3(wD[j], wD[j + 1], wD[j + 2]),
                                   fmaxf(wC[j], wC[j + 2])));
            bool pk = in && (h > 0.1f) && (nm <= h);
            unsigned mask = __ballot_sync(0xffffffffu, pk);
            if (pk) {
                int leader = __ffs(mask) - 1;
                int base;
                if (lane == leader) base = atomicAdd(&s_cnt, __popc(mask));
                base = __shfl_sync(mask, base, leader);
                int pos = base + __popc(mask & ((1u << lane) - 1u));
                if (pos < SLCAP) {
                    slist[pos] = ((unsigned long long)__float_as_uint(h) << 32) |
                                 (unsigned long long)(0xFFFFFFFFu - (unsigned)(i + j));
                }
            }
        }
    }
    __syncthreads();

    const int cnt = (s_cnt < SLCAP) ? s_cnt : SLCAP;
    if (threadIdx.x == 0) s_base = atomicAdd(&g_cnt[ch], cnt);
    __syncthreads();
    const int base = s_base;
    for (int t = threadIdx.x; t < cnt; t += T1) {
        int pos = base + t;
        if (pos < CAP) g_list[ch][pos] = slist[t];
    }
}

// ---------------------------------------------------------------------------
// Select: one block per channel.  Histogram radix-select over the candidate
// list -> survivors -> warp argmax x30 -> subpixel refine (global heat reads).
// ---------------------------------------------------------------------------
__global__ void __launch_bounds__(T1) select_kernel(const float* __restrict__ heat,
                                                    float* __restrict__ out_peaks)
{
    __shared__ unsigned hist[NBINS];
    __shared__ unsigned long long surv[SCAP];
    __shared__ unsigned long long s_top[Pn];
    __shared__ int s_sc, s_cut, s_m;

    const int ch = blockIdx.x;
    const unsigned long long* list = g_list[ch];
    const float* hp = heat + (size_t)ch * HW;
    const int lane = threadIdx.x & 31;

    for (int i = threadIdx.x; i < NBINS; i += T1) hist[i] = 0;
    if (threadIdx.x == 0) {
        int m = g_cnt[ch];
        s_m = (m < CAP) ? m : CAP;
        s_sc = 0; s_cut = 0;
    }
    __syncthreads();

    const int m = s_m;
    for (int i = threadIdx.x; i < m; i += T1) {
        float h = __uint_as_float((unsigned)(list[i] >> 32));
        atomicAdd(&hist[bin_of(h)], 1u);
    }
    __syncthreads();

    // cutoff bin = highest bin whose suffix count >= Pn
    if (threadIdx.x < 32) {
        int acc = 0, cut = 0;
        for (int base = NBINS - 32; base >= 0; base -= 32) {
            int s = (int)hist[base + lane];
            #pragma unroll
            for (int off = 1; off < 32; off <<= 1) {
                int t = __shfl_down_sync(0xffffffffu, s, off);
                if (lane + off < 32) s += t;
            }
            int chunk_total = __shfl_sync(0xffffffffu, s, 0);
            if (acc + chunk_total >= Pn) {
                unsigned msk = __ballot_sync(0xffffffffu, acc + s >= Pn);
                cut = base + (31 - __clz(msk));
                break;
            }
            acc += chunk_total;
        }
        if (lane == 0) s_cut = cut;
    }
    __syncthreads();

    // compact survivors (bin >= cut)
    const int cut = s_cut;
    const int m_pad = (m + T1 - 1) / T1 * T1;
    for (int i = threadIdx.x; i < m_pad; i += T1) {
        bool keep = false;
        unsigned long long key = 0ull;
        if (i < m) {
            key = list[i];
            keep = bin_of(__uint_as_float((unsigned)(key >> 32))) >= cut;
        }
        unsigned mask = __ballot_sync(0xffffffffu, keep);
        if (keep) {
            int leader = __ffs(mask) - 1;
            int base;
            if (lane == leader) base = atomicAdd(&s_sc, __popc(mask));
            base = __shfl_sync(mask, base, leader);
            int pos = base + __popc(mask & ((1u << lane) - 1u));
            if (pos < SCAP) surv[pos] = key;
        }
    }
    __syncthreads();

    if (threadIdx.x < 32) {
        const int n = (s_sc < SCAP) ? s_sc : SCAP;
        for (int p = 0; p < Pn; ++p) {
            unsigned long long best = 0ull;
            int bpos = -1;
            for (int i = lane; i < n; i += 32) {
                unsigned long long c = surv[i];
                if (c > best) { best = c; bpos = i; }
            }
            #pragma unroll
            for (int off = 16; off > 0; off >>= 1) {
                unsigned long long ob = __shfl_down_sync(0xffffffffu, best, off);
                int op = __shfl_down_sync(0xffffffffu, bpos, off);
                if (ob > best) { best = ob; bpos = op; }
            }
            best = __shfl_sync(0xffffffffu, best, 0);
            bpos = __shfl_sync(0xffffffffu, bpos, 0);
            if (lane == 0) {
                s_top[p] = best;
                if (bpos >= 0) surv[bpos] = 0ull;
            }
            __syncwarp();
        }

        if (lane < Pn) {
            unsigned long long key = s_top[lane];
            float px = 0.f, py = 0.f, sc = 0.f;
            if (key != 0ull) {
                unsigned idx = 0xFFFFFFFFu - (unsigned)(key & 0xFFFFFFFFu);
                float h = __uint_as_float((unsigned)(key >> 32));
                int y = idx / Wdim;
                int x = idx - y * Wdim;
                float dx = 0.f, dy = 0.f;
                if (y > 0 && y < Hdim - 1 && x > 0 && x < Wdim - 1) {
                    float r = __ldg(hp + idx + 1),    l = __ldg(hp + idx - 1);
                    float d = __ldg(hp + idx + Wdim), u = __ldg(hp + idx - Wdim);
                    float dxr = 0.5f * (r - l);
                    float dxx = (r + l) - 2.0f * h;
                    dx = (fabsf(dxx) > 1e-6f) ? (dxr / (-dxx)) : dxr;
                    float dyr = 0.5f * (d - u);
                    float dyy = (d + u) - 2.0f * h;
                    dy = (fabsf(dyy) > 1e-6f) ? (dyr / (-dyy)) : dyr;
                }
                px = (float)x + dx;
                py = (float)y + dy;
                sc = h;
            }
            float* o = out_peaks + ((size_t)ch * Pn + lane) * 3;
            o[0] = px; o[1] = py; o[2] = sc;
        }
    }
}

// ---------------------------------------------------------------------------
// Stage 2: per-(b,l) limb — one PAF channel in smem at a time (100KB) so two
// blocks co-reside per SM and loads overlap compute across blocks.
// ---------------------------------------------------------------------------
__global__ void __launch_bounds__(T2, 2) stage2_kernel(const float* __restrict__ paf,
                                                       const float* __restrict__ peaks,
                                                       float* __restrict__ conn)
{
    extern __shared__ float s2[];                // HW floats (reused x then y)

    __shared__ float sax[Pn], say[Pn], sas[Pn];
    __shared__ float sbx[Pn], sby[Pn], sbs[Pn];

    const int bl = blockIdx.x;      // b*Ln + l
    const int b = bl / Ln;
    const int l = bl - b * Ln;

    const float4* gx = (const float4*)(paf + ((size_t)b * 38 + 2 * l) * HW);
    const float4* gy = (const float4*)(paf + ((size_t)b * 38 + 2 * l + 1) * HW);

    for (int i = threadIdx.x; i < NG; i += T2)
        cp16(&((float4*)s2)[i], &gx[i]);
    cp_commit();

    const int ja = c_skel_a[l];
    const int jb = c_skel_b[l];
    if (threadIdx.x < Pn) {
        const float* pa = peaks + ((size_t)(b * Kdim + ja) * Pn + threadIdx.x) * 3;
        sax[threadIdx.x] = pa[0]; say[threadIdx.x] = pa[1]; sas[threadIdx.x] = pa[2];
    } else if (threadIdx.x >= 32 && threadIdx.x < 32 + Pn) {
        int j = threadIdx.x - 32;
        const float* pb = peaks + ((size_t)(b * Kdim + jb) * Pn + j) * 3;
        sbx[j] = pb[0]; sby[j] = pb[1]; sbs[j] = pb[2];
    }

    cp_wait<0>();
    __syncthreads();

    int   lin[2][Sn];
    float xp [2][Sn];
    float vyv[2];
    float halfs[2];
    bool  pv[2];
    const float step = 1.0f / 9.0f;

    #pragma unroll
    for (int q = 0; q < 2; ++q) {
        int pr = threadIdx.x + q * T2;
        bool act = (pr < Pn * Pn);
        int i = act ? (pr / Pn) : 0;
        int j = act ? (pr - i * Pn) : 0;
        float ax = sax[i], ay = say[i], sa = sas[i];
        float bx = sbx[j], by = sby[j], sb = sbs[j];
        bool valid = act && (sa > 0.1f) && (sb > 0.1f);
        pv[q] = valid;
        halfs[q] = 0.5f * (sa + sb);
        float dxl = bx - ax;
        float dyl = by - ay;
        float norm = sqrtf(__fadd_rn(__fmul_rn(dxl, dxl), __fmul_rn(dyl, dyl))) + 1e-8f;
        float vx = dxl / norm;
        float vy = dyl / norm;
        vyv[q] = vy;
        #pragma unroll
        for (int s = 0; s < Sn; ++s) {
            float t = (float)s * step;
            // no-FMA: a ulp flip at a .5 boundary changes the gathered cell
            float xs = __fadd_rn(ax, __fmul_rn(t, dxl));
            float ys = __fadd_rn(ay, __fmul_rn(t, dyl));
            float fx = fminf(fmaxf(rintf(xs), 0.0f), (float)(Wdim - 1));
            float fy = fminf(fmaxf(rintf(ys), 0.0f), (float)(Hdim - 1));
            int li = valid ? ((int)fy * Wdim + (int)fx) : 0;
            lin[q][s] = li;
            xp[q][s] = __fmul_rn(s2[li], vx);
        }
    }
    __syncthreads();                 // all pafx reads done; buffer free

    for (int i = threadIdx.x; i < NG; i += T2)
        cp16(&((float4*)s2)[i], &gy[i]);
    cp_commit();
    cp_wait<0>();
    __syncthreads();

    float* co = conn + (size_t)bl * Pn * Pn;
    #pragma unroll
    for (int q = 0; q < 2; ++q) {
        int pr = threadIdx.x + q * T2;
        bool act = (pr < Pn * Pn);
        float sum = 0.0f;
        int c = 0;
        #pragma unroll
        for (int s = 0; s < Sn; ++s) {
            float v = __fadd_rn(xp[q][s], __fmul_rn(s2[lin[q][s]], vyv[q]));
            sum = __fadd_rn(sum, v);
            c += (v > 0.05f) ? 1 : 0;
        }
        float outv = 0.0f;
        if (pv[q]) {
            float mean = sum / 10.0f;
            float ratio = (float)c / 10.0f;
            if (mean > 0.0f && ratio > 0.8f)
                outv = mean + halfs[q];
        }
        if (act) co[pr] = outv;
    }
}

// ---------------------------------------------------------------------------
extern "C" void kernel_launch(void* const* d_in, const int* in_sizes, int n_in,
                              void* d_out, int out_size)
{
    const float* heat = (const float*)d_in[0];
    const float* paf  = (const float*)d_in[1];
    float* out   = (float*)d_out;
    float* peaks = out;                                  // B*K*P*3 = 48960
    float* conn  = out + (size_t)Bdim * Kdim * Pn * 3;   // B*L*P*P = 547200

    const int smem2 = HW * 4;                            // 102400 -> 2 blocks/SM
    cudaFuncSetAttribute(stage2_kernel, cudaFuncAttributeMaxDynamicSharedMemorySize, smem2);

    init_kernel<<<1, NCH>>>();
    detect_kernel<<<NCH * SLABS, T1>>>(heat);
    select_kernel<<<NCH, T1>>>(heat, peaks);
    stage2_kernel<<<Bdim * Ln, T2, smem2>>>(paf, peaks, conn);
}

// round 5
// speedup vs baseline: 1.1561x; 1.1561x over previous
#include <cuda_runtime.h>
#include <cstdint>

#define Bdim 32
#define Kdim 17
#define Hdim 160
#define Wdim 160
#define HW   (Hdim*Wdim)
#define W4   (Wdim/4)
#define NG   (HW/4)
#define Pn   30
#define Sn   10
#define Ln   19
#define NCH  (Bdim*Kdim)
#define T1   256
#define T2   512
#define NBINS 1024
#define SCAP  256
#define NEGF  (-1.0e30f)

__constant__ int c_skel_a[Ln] = {15,13,16,14,11, 5, 6, 5, 5, 6, 7, 8, 1, 0, 0, 1, 2, 3, 4};
__constant__ int c_skel_b[Ln] = {13,11,14,12,12,11,12, 6, 7, 8, 9,10, 2, 1, 2, 3, 4, 5, 6};

// ---------------- cp.async helpers ----------------
__device__ __forceinline__ void cp16(void* s, const void* g) {
    unsigned sa = (unsigned)__cvta_generic_to_shared(s);
    asm volatile("cp.async.cg.shared.global [%0], [%1], 16;\n" :: "r"(sa), "l"(g));
}
__device__ __forceinline__ void cp_commit() { asm volatile("cp.async.commit_group;\n"); }
template <int N>
__device__ __forceinline__ void cp_wait() { asm volatile("cp.async.wait_group %0;\n" :: "n"(N)); }

// monotone bin: v = h^9 (uniform-izes max-of-9 peak-score distribution)
__device__ __forceinline__ int bin_of(float h) {
    float h2 = h * h;
    float h4 = h2 * h2;
    float v  = h4 * h4 * h;
    int b = (int)(v * (float)NBINS);
    return b < 0 ? 0 : (b > NBINS - 1 ? NBINS - 1 : b);
}

__device__ __forceinline__ float max3(float a, float b, float c) {
    return fmaxf(fmaxf(a, b), c);
}

// detect 4 pixels of group g; histogram peaks; return 4-bit peak pattern
__device__ __forceinline__ unsigned detect4(const float* __restrict__ hp,
                                            const float4* __restrict__ hp4,
                                            int g, unsigned* hist)
{
    int y  = g / W4;
    int xq = g - y * W4;
    int i  = g * 4;
    bool up = (y > 0), dn = (y < Hdim - 1);
    bool lf = (xq > 0), rt = (xq < W4 - 1);

    float4 nf = make_float4(NEGF, NEGF, NEGF, NEGF);
    float4 C = hp4[g];
    float4 U = up ? hp4[g - W4] : nf;
    float4 D = dn ? hp4[g + W4] : nf;
    float lC =  lf        ? __ldg(hp + i - 1)        : NEGF;
    float rC =  rt        ? __ldg(hp + i + 4)        : NEGF;
    float lU = (lf && up) ? __ldg(hp + i - Wdim - 1) : NEGF;
    float rU = (rt && up) ? __ldg(hp + i - Wdim + 4) : NEGF;
    float lD = (lf && dn) ? __ldg(hp + i + Wdim - 1) : NEGF;
    float rD = (rt && dn) ? __ldg(hp + i + Wdim + 4) : NEGF;

    float wU[6] = {lU, U.x, U.y, U.z, U.w, rU};
    float wC[6] = {lC, C.x, C.y, C.z, C.w, rC};
    float wD[6] = {lD, D.x, D.y, D.z, D.w, rD};

    unsigned pat = 0;
    #pragma unroll
    for (int j = 0; j < 4; ++j) {
        float h  = wC[j + 1];
        float nm = fmaxf(max3(wU[j], wU[j + 1], wU[j + 2]),
                         fmaxf(max3(wD[j], wD[j + 1], wD[j + 2]),
                               fmaxf(wC[j], wC[j + 2])));
        bool pk = (h > 0.1f) && (nm <= h);
        if (pk) {
            pat |= (1u << j);
            atomicAdd(&hist[bin_of(h)], 1u);
        }
    }
    return pat;
}

// ---------------------------------------------------------------------------
// Stage 1: one block per (b,k) channel.
//  pass1: stream heat, peak-detect -> register bitmask + smem histogram
//  warp0: cutoff bin for top-30
//  pass2: replay own bitmask, collect survivors >= cutoff (plain atomic, rare)
//  warp0: 30x argmax + subpixel refine
// ---------------------------------------------------------------------------
__global__ void __launch_bounds__(T1) stage1_kernel(const float* __restrict__ heat,
                                                    float* __restrict__ out_peaks)
{
    __shared__ unsigned hist[NBINS];
    __shared__ unsigned long long surv[SCAP];
    __shared__ unsigned long long s_top[Pn];
    __shared__ int s_sc, s_cut;

    const int ch = blockIdx.x;
    const float* hp = heat + (size_t)ch * HW;
    const float4* hp4 = (const float4*)hp;
    const int lane = threadIdx.x & 31;

    for (int i = threadIdx.x; i < NBINS; i += T1) hist[i] = 0;
    if (threadIdx.x == 0) { s_sc = 0; s_cut = 0; }
    __syncthreads();

    // ---- pass 1: NG = 25*T1 groups exactly; bitmask words fixed per sub-loop
    unsigned m0 = 0, m1 = 0, m2 = 0, m3 = 0;
    for (int it = 0; it < 8; ++it)
        m0 |= detect4(hp, hp4, it * T1 + threadIdx.x, hist) << ((it & 7) * 4);
    for (int it = 8; it < 16; ++it)
        m1 |= detect4(hp, hp4, it * T1 + threadIdx.x, hist) << ((it & 7) * 4);
    for (int it = 16; it < 24; ++it)
        m2 |= detect4(hp, hp4, it * T1 + threadIdx.x, hist) << ((it & 7) * 4);
    m3 = detect4(hp, hp4, 24 * T1 + threadIdx.x, hist);
    __syncthreads();

    // ---- warp 0: cutoff bin = highest bin whose suffix count >= Pn
    if (threadIdx.x < 32) {
        int acc = 0, cut = 0;
        for (int base = NBINS - 32; base >= 0; base -= 32) {
            int s = (int)hist[base + lane];
            #pragma unroll
            for (int off = 1; off < 32; off <<= 1) {
                int t = __shfl_down_sync(0xffffffffu, s, off);
                if (lane + off < 32) s += t;
            }
            int chunk_total = __shfl_sync(0xffffffffu, s, 0);
            if (acc + chunk_total >= Pn) {
                unsigned msk = __ballot_sync(0xffffffffu, acc + s >= Pn);
                cut = base + (31 - __clz(msk));
                break;
            }
            acc += chunk_total;
        }
        if (lane == 0) s_cut = cut;
    }
    __syncthreads();

    // ---- pass 2: replay bitmask, keep bins >= cut (rare -> plain atomics)
    const int cut = s_cut;
    unsigned mw[4] = {m0, m1, m2, m3};
    #pragma unroll
    for (int w = 0; w < 4; ++w) {
        unsigned m = mw[w];
        while (m) {
            int b = __ffs(m) - 1;
            m &= m - 1;
            int bitidx = w * 32 + b;
            int it = bitidx >> 2;
            int j  = bitidx & 3;
            int i  = (it * T1 + threadIdx.x) * 4 + j;
            float h = __ldg(hp + i);
            if (bin_of(h) >= cut) {
                int pos = atomicAdd(&s_sc, 1);
                if (pos < SCAP) {
                    surv[pos] = ((unsigned long long)__float_as_uint(h) << 32) |
                                (unsigned long long)(0xFFFFFFFFu - (unsigned)i);
                }
            }
        }
    }
    __syncthreads();

    // ---- warp 0: 30 argmax rounds + subpixel refine
    if (threadIdx.x < 32) {
        const int n = (s_sc < SCAP) ? s_sc : SCAP;
        for (int p = 0; p < Pn; ++p) {
            unsigned long long best = 0ull;
            int bpos = -1;
            for (int i = lane; i < n; i += 32) {
                unsigned long long c = surv[i];
                if (c > best) { best = c; bpos = i; }
            }
            #pragma unroll
            for (int off = 16; off > 0; off >>= 1) {
                unsigned long long ob = __shfl_down_sync(0xffffffffu, best, off);
                int op = __shfl_down_sync(0xffffffffu, bpos, off);
                if (ob > best) { best = ob; bpos = op; }
            }
            best = __shfl_sync(0xffffffffu, best, 0);
            bpos = __shfl_sync(0xffffffffu, bpos, 0);
            if (lane == 0) {
                s_top[p] = best;
                if (bpos >= 0) surv[bpos] = 0ull;
            }
            __syncwarp();
        }

        if (lane < Pn) {
            unsigned long long key = s_top[lane];
            float px = 0.f, py = 0.f, sc = 0.f;
            if (key != 0ull) {
                unsigned idx = 0xFFFFFFFFu - (unsigned)(key & 0xFFFFFFFFu);
                float h = __uint_as_float((unsigned)(key >> 32));
                int y = idx / Wdim;
                int x = idx - y * Wdim;
                float dx = 0.f, dy = 0.f;
                if (y > 0 && y < Hdim - 1 && x > 0 && x < Wdim - 1) {
                    float r = __ldg(hp + idx + 1),    l = __ldg(hp + idx - 1);
                    float d = __ldg(hp + idx + Wdim), u = __ldg(hp + idx - Wdim);
                    float dxr = 0.5f * (r - l);
                    float dxx = (r + l) - 2.0f * h;
                    dx = (fabsf(dxx) > 1e-6f) ? (dxr / (-dxx)) : dxr;
                    float dyr = 0.5f * (d - u);
                    float dyy = (d + u) - 2.0f * h;
                    dy = (fabsf(dyy) > 1e-6f) ? (dyr / (-dyy)) : dyr;
                }
                px = (float)x + dx;
                py = (float)y + dy;
                sc = h;
            }
            float* o = out_peaks + ((size_t)ch * Pn + lane) * 3;
            o[0] = px; o[1] = py; o[2] = sc;
        }
    }
}

// ---------------------------------------------------------------------------
// Stage 2: per-(b,l) limb — one PAF channel in smem at a time (100KB) so two
// blocks co-reside per SM and loads overlap compute across blocks.
// ---------------------------------------------------------------------------
__global__ void __launch_bounds__(T2, 2) stage2_kernel(const float* __restrict__ paf,
                                                       const float* __restrict__ peaks,
                                                       float* __restrict__ conn)
{
    extern __shared__ float s2[];                // HW floats (reused x then y)

    __shared__ float sax[Pn], say[Pn], sas[Pn];
    __shared__ float sbx[Pn], sby[Pn], sbs[Pn];

    const int bl = blockIdx.x;      // b*Ln + l
    const int b = bl / Ln;
    const int l = bl - b * Ln;

    const float4* gx = (const float4*)(paf + ((size_t)b * 38 + 2 * l) * HW);
    const float4* gy = (const float4*)(paf + ((size_t)b * 38 + 2 * l + 1) * HW);

    for (int i = threadIdx.x; i < NG; i += T2)
        cp16(&((float4*)s2)[i], &gx[i]);
    cp_commit();

    const int ja = c_skel_a[l];
    const int jb = c_skel_b[l];
    if (threadIdx.x < Pn) {
        const float* pa = peaks + ((size_t)(b * Kdim + ja) * Pn + threadIdx.x) * 3;
        sax[threadIdx.x] = pa[0]; say[threadIdx.x] = pa[1]; sas[threadIdx.x] = pa[2];
    } else if (threadIdx.x >= 32 && threadIdx.x < 32 + Pn) {
        int j = threadIdx.x - 32;
        const float* pb = peaks + ((size_t)(b * Kdim + jb) * Pn + j) * 3;
        sbx[j] = pb[0]; sby[j] = pb[1]; sbs[j] = pb[2];
    }

    cp_wait<0>();
    __syncthreads();

    int   lin[2][Sn];
    float xp [2][Sn];
    float vyv[2];
    float halfs[2];
    bool  pv[2];
    const float step = 1.0f / 9.0f;

    #pragma unroll
    for (int q = 0; q < 2; ++q) {
        int pr = threadIdx.x + q * T2;
        bool act = (pr < Pn * Pn);
        int i = act ? (pr / Pn) : 0;
        int j = act ? (pr - i * Pn) : 0;
        float ax = sax[i], ay = say[i], sa = sas[i];
        float bx = sbx[j], by = sby[j], sb = sbs[j];
        bool valid = act && (sa > 0.1f) && (sb > 0.1f);
        pv[q] = valid;
        halfs[q] = 0.5f * (sa + sb);
        float dxl = bx - ax;
        float dyl = by - ay;
        float norm = sqrtf(__fadd_rn(__fmul_rn(dxl, dxl), __fmul_rn(dyl, dyl))) + 1e-8f;
        float vx = dxl / norm;
        float vy = dyl / norm;
        vyv[q] = vy;
        #pragma unroll
        for (int s = 0; s < Sn; ++s) {
            float t = (float)s * step;
            // no-FMA: a ulp flip at a .5 boundary changes the gathered cell
            float xs = __fadd_rn(ax, __fmul_rn(t, dxl));
            float ys = __fadd_rn(ay, __fmul_rn(t, dyl));
            float fx = fminf(fmaxf(rintf(xs), 0.0f), (float)(Wdim - 1));
            float fy = fminf(fmaxf(rintf(ys), 0.0f), (float)(Hdim - 1));
            int li = valid ? ((int)fy * Wdim + (int)fx) : 0;
            lin[q][s] = li;
            xp[q][s] = __fmul_rn(s2[li], vx);
        }
    }
    __syncthreads();                 // all pafx reads done; buffer free

    for (int i = threadIdx.x; i < NG; i += T2)
        cp16(&((float4*)s2)[i], &gy[i]);
    cp_commit();
    cp_wait<0>();
    __syncthreads();

    float* co = conn + (size_t)bl * Pn * Pn;
    #pragma unroll
    for (int q = 0; q < 2; ++q) {
        int pr = threadIdx.x + q * T2;
        bool act = (pr < Pn * Pn);
        float sum = 0.0f;
        int c = 0;
        #pragma unroll
        for (int s = 0; s < Sn; ++s) {
            float v = __fadd_rn(xp[q][s], __fmul_rn(s2[lin[q][s]], vyv[q]));
            sum = __fadd_rn(sum, v);
            c += (v > 0.05f) ? 1 : 0;
        }
        float outv = 0.0f;
        if (pv[q]) {
            float mean = sum / 10.0f;
            float ratio = (float)c / 10.0f;
            if (mean > 0.0f && ratio > 0.8f)
                outv = mean + halfs[q];
        }
        if (act) co[pr] = outv;
    }
}

// ---------------------------------------------------------------------------
extern "C" void kernel_launch(void* const* d_in, const int* in_sizes, int n_in,
                              void* d_out, int out_size)
{
    const float* heat = (const float*)d_in[0];
    const float* paf  = (const float*)d_in[1];
    float* out   = (float*)d_out;
    float* peaks = out;                                  // B*K*P*3 = 48960
    float* conn  = out + (size_t)Bdim * Kdim * Pn * 3;   // B*L*P*P = 547200

    const int smem2 = HW * 4;                            // 102400 -> 2 blocks/SM
    cudaFuncSetAttribute(stage2_kernel, cudaFuncAttributeMaxDynamicSharedMemorySize, smem2);

    stage1_kernel<<<NCH, T1>>>(heat, peaks);
    stage2_kernel<<<Bdim * Ln, T2, smem2>>>(paf, peaks, conn);
}